// round 7
// baseline (speedup 1.0000x reference)
#include <cuda_runtime.h>
#include <cuda_fp16.h>
#include <cstdint>

#define KDIM 4096
#define NDIM 11008
#define MDIM 4096
#define BM 128
#define BN 128
#define BK 64
#define STRIDE 72                 // padded row stride in halves (144 B)
#define STAGE_ELEMS (128 * STRIDE)
#define SMEM_BYTES (4 * STAGE_ELEMS * 2)   // A0,A1,B0,B1 = 73728 B -> 2 CTAs/SM
#define NUM_KT (KDIM / BK)        // 64

// fp16 copies (harness supplies float32 for the reference's float16 tensors)
__device__ __half g_xh[(size_t)MDIM * KDIM];   // activations fp16
__device__ __half g_w[(size_t)NDIM * KDIM];    // dequantized weights [N, K] fp16

__global__ void cvt_x_kernel(const float* __restrict__ x) {
    size_t i = ((size_t)blockIdx.x * blockDim.x + threadIdx.x) * 4;
    float4 v = *(const float4*)(x + i);
    __half2 h0 = __floats2half2_rn(v.x, v.y);
    __half2 h1 = __floats2half2_rn(v.z, v.w);
    uint2 st;
    st.x = *(uint32_t*)&h0;
    st.y = *(uint32_t*)&h1;
    *(uint2*)(g_xh + i) = st;
}

// One-time dequant: packed [K/8, N] int32 + scales [K/128, N] -> W [N, K] fp16.
__global__ void dequant_w_kernel(const int* __restrict__ packed,
                                 const float* __restrict__ scales) {
    const int n   = blockIdx.x * 256 + threadIdx.x;
    const int kwb = blockIdx.y * 4;                   // 4 words = 32 k, one group
    const __half2 sc2 = __half2half2(__float2half_rn(scales[(size_t)(kwb >> 4) * NDIM + n]));
    const __half2 off1032 = __halves2half2(__ushort_as_half((unsigned short)0x6408),
                                           __ushort_as_half((unsigned short)0x6408));
    __half* dst = g_w + (size_t)n * KDIM + kwb * 8;
#pragma unroll
    for (int i = 0; i < 4; i++) {
        uint32_t w = (uint32_t)packed[(size_t)(kwb + i) * NDIM + n];
        uint32_t r[4];
#pragma unroll
        for (int j = 0; j < 4; j++) {
            uint32_t v = w >> (8 * j);
            uint32_t p = ((v & 0xFu) | ((v & 0xF0u) << 12)) | 0x64006400u;
            __half2 h = __hmul2(__hsub2(*(__half2*)&p, off1032), sc2);
            r[j] = *(uint32_t*)&h;
        }
        *(uint4*)(dst + i * 8) = make_uint4(r[0], r[1], r[2], r[3]);
    }
}

__device__ __forceinline__ void cp_async16(uint32_t saddr, const void* gptr) {
    asm volatile("cp.async.cg.shared.global [%0], [%1], 16;\n" :: "r"(saddr), "l"(gptr));
}
__device__ __forceinline__ void cp_commit() { asm volatile("cp.async.commit_group;\n"); }
__device__ __forceinline__ void cp_wait0()  { asm volatile("cp.async.wait_group 0;\n"); }

__device__ __forceinline__ void ldmatrix_x4(uint32_t& r0, uint32_t& r1, uint32_t& r2, uint32_t& r3, uint32_t addr) {
    asm volatile("ldmatrix.sync.aligned.m8n8.x4.shared.b16 {%0,%1,%2,%3}, [%4];\n"
                 : "=r"(r0), "=r"(r1), "=r"(r2), "=r"(r3) : "r"(addr));
}

// f16-accumulate mma: D,C are 4 halves in 2 b32 regs (same thread-cell layout as f32 path)
__device__ __forceinline__ void mma16816_f16(uint32_t& c0, uint32_t& c1,
                                             const uint32_t* a, const uint32_t* b) {
    asm volatile(
        "mma.sync.aligned.m16n8k16.row.col.f16.f16.f16.f16 "
        "{%0,%1}, {%2,%3,%4,%5}, {%6,%7}, {%0,%1};\n"
        : "+r"(c0), "+r"(c1)
        : "r"(a[0]), "r"(a[1]), "r"(a[2]), "r"(a[3]), "r"(b[0]), "r"(b[1]));
}

__global__ __launch_bounds__(256, 2)
void qlinear_kernel(const float* __restrict__ bias, float* __restrict__ out)
{
    extern __shared__ __half smem[];
    const uint32_t smem_base = (uint32_t)__cvta_generic_to_shared(smem);

    const int tid  = threadIdx.x;
    const int lane = tid & 31;
    const int warp = tid >> 5;
    const int wm   = warp & 1;    // 2 warps along M (64 rows each)
    const int wn   = warp >> 1;   // 4 warps along N (32 cols each)

    const int bm = blockIdx.y * BM;
    const int bn = blockIdx.x * BN;

    float acc[4][4][4];
#pragma unroll
    for (int i = 0; i < 4; i++)
#pragma unroll
        for (int j = 0; j < 4; j++)
#pragma unroll
            for (int k = 0; k < 4; k++) acc[i][j][k] = 0.f;

    // layout: A0 | A1 | B0 | B1, each STAGE_ELEMS halves
    const int crow = tid >> 3;
    const int ccc  = tid & 7;

    auto issue_stage = [&](int buf, int kb) {
        const uint32_t abase = smem_base + (uint32_t)(buf * STAGE_ELEMS * 2);
        const uint32_t bbase = smem_base + (uint32_t)((2 + buf) * STAGE_ELEMS * 2);
#pragma unroll
        for (int i = 0; i < 4; i++) {
            int row = crow + 32 * i;
            uint32_t soff = (uint32_t)((row * STRIDE + ccc * 8) * 2);
            cp_async16(abase + soff, g_xh + (size_t)(bm + row) * KDIM + kb + ccc * 8);
            cp_async16(bbase + soff, g_w  + (size_t)(bn + row) * KDIM + kb + ccc * 8);
        }
        cp_commit();
    };

    issue_stage(0, 0);
    cp_wait0();
    __syncthreads();

    const int arow  = wm * 64 + (lane & 15);
    const int acolg = (lane >> 4) * 8;
    const int brow  = wn * 32 + (lane & 15);

    for (int kt = 0; kt < NUM_KT; ++kt) {
        const int buf = kt & 1;
        const bool has_next = (kt + 1) < NUM_KT;

        if (has_next)
            issue_stage(buf ^ 1, (kt + 1) * BK);   // overlaps with compute below

        const uint32_t abase = smem_base + (uint32_t)(buf * STAGE_ELEMS * 2);
        const uint32_t bbase = smem_base + (uint32_t)((2 + buf) * STAGE_ELEMS * 2);

#pragma unroll
        for (int kp = 0; kp < 2; kp++) {           // pair of k-slices (K=32 f16 chain)
            uint32_t a[4][2][4];
#pragma unroll
            for (int mt = 0; mt < 4; mt++) {
#pragma unroll
                for (int s = 0; s < 2; s++) {
                    uint32_t addr = abase + (uint32_t)(((arow + mt * 16) * STRIDE
                                     + (2 * kp + s) * 16 + acolg) * 2);
                    ldmatrix_x4(a[mt][s][0], a[mt][s][1], a[mt][s][2], a[mt][s][3], addr);
                }
            }
            uint32_t b[4][2][2];
#pragma unroll
            for (int nt2 = 0; nt2 < 2; nt2++) {
#pragma unroll
                for (int s = 0; s < 2; s++) {
                    uint32_t r0, r1, r2, r3;
                    uint32_t addr = bbase + (uint32_t)(((brow + nt2 * 16) * STRIDE
                                     + (2 * kp + s) * 16 + acolg) * 2);
                    ldmatrix_x4(r0, r1, r2, r3, addr);
                    b[2 * nt2][s][0] = r0;     b[2 * nt2][s][1] = r2;
                    b[2 * nt2 + 1][s][0] = r1; b[2 * nt2 + 1][s][1] = r3;
                }
            }
#pragma unroll
            for (int mt = 0; mt < 4; mt++) {
#pragma unroll
                for (int nt = 0; nt < 4; nt++) {
                    uint32_t c0 = 0, c1 = 0;
                    mma16816_f16(c0, c1, a[mt][0], b[nt][0]);
                    mma16816_f16(c0, c1, a[mt][1], b[nt][1]);
                    float2 f0 = __half22float2(*(__half2*)&c0);
                    float2 f1 = __half22float2(*(__half2*)&c1);
                    acc[mt][nt][0] += f0.x;
                    acc[mt][nt][1] += f0.y;
                    acc[mt][nt][2] += f1.x;
                    acc[mt][nt][3] += f1.y;
                }
            }
        }

        if (has_next) cp_wait0();   // copies had the whole compute phase to land
        __syncthreads();
    }

    // ---------- epilogue: f32 out, rounded through fp16 to match reference ----------
#pragma unroll
    for (int mt = 0; mt < 4; mt++) {
#pragma unroll
        for (int nt = 0; nt < 4; nt++) {
            int row0 = bm + wm * 64 + mt * 16 + (lane >> 2);
            int col  = bn + wn * 32 + nt * 8 + (lane & 3) * 2;
            float2 bf = *(const float2*)(bias + col);
            float2 v0, v1;
            v0.x = __half2float(__float2half_rn(acc[mt][nt][0] + bf.x));
            v0.y = __half2float(__float2half_rn(acc[mt][nt][1] + bf.y));
            v1.x = __half2float(__float2half_rn(acc[mt][nt][2] + bf.x));
            v1.y = __half2float(__float2half_rn(acc[mt][nt][3] + bf.y));
            *(float2*)(out + (size_t)row0 * NDIM + col) = v0;
            *(float2*)(out + (size_t)(row0 + 8) * NDIM + col) = v1;
        }
    }
}

extern "C" void kernel_launch(void* const* d_in, const int* in_sizes, int n_in,
                              void* d_out, int out_size) {
    const float* x      = (const float*)d_in[0];
    const int*   packed = (const int*)d_in[1];
    const float* scales = (const float*)d_in[2];
    const float* bias   = (const float*)d_in[3];
    float*       out    = (float*)d_out;

    // prepass 1: x (f32) -> g_xh (fp16)
    const size_t n_x = (size_t)MDIM * KDIM;
    cvt_x_kernel<<<(unsigned)(n_x / 4 / 256), 256>>>(x);

    // prepass 2: packed int4 -> g_w (fp16, [N, K]) — once, keeps mainloop lean
    dim3 dq_grid(NDIM / 256, KDIM / 32);
    dequant_w_kernel<<<dq_grid, 256>>>(packed, scales);

    cudaFuncSetAttribute(qlinear_kernel, cudaFuncAttributeMaxDynamicSharedMemorySize, SMEM_BYTES);
    dim3 grid(NDIM / BN, MDIM / BM);
    qlinear_kernel<<<grid, 256, SMEM_BYTES>>>(bias, out);
}

// round 8
// speedup vs baseline: 1.2379x; 1.2379x over previous
#include <cuda_runtime.h>
#include <cuda_fp16.h>
#include <cstdint>

#define KDIM 4096
#define NDIM 11008
#define MDIM 4096
#define BM 64
#define BN 128
#define BK 64
#define STRIDE 72                        // padded row stride in halves (144 B)
#define A_ELEMS (BM * STRIDE)            // 4608 halves
#define B_ELEMS (BN * STRIDE)            // 9216 halves
#define SMEM_BYTES (2 * (A_ELEMS + B_ELEMS) * 2)   // 55296 B -> 3 CTAs/SM
#define NUM_KT (KDIM / BK)               // 64

// fp16 copy of x (harness provides float32 for the reference's float16 tensors)
__device__ __half g_xh[(size_t)MDIM * KDIM];

__global__ void cvt_x_kernel(const float* __restrict__ x) {
    size_t i = ((size_t)blockIdx.x * blockDim.x + threadIdx.x) * 4;
    float4 v = *(const float4*)(x + i);
    __half2 h0 = __floats2half2_rn(v.x, v.y);
    __half2 h1 = __floats2half2_rn(v.z, v.w);
    uint2 st;
    st.x = *(uint32_t*)&h0;
    st.y = *(uint32_t*)&h1;
    *(uint2*)(g_xh + i) = st;
}

__device__ __forceinline__ void cp_async16(uint32_t saddr, const void* gptr) {
    asm volatile("cp.async.cg.shared.global [%0], [%1], 16;\n" :: "r"(saddr), "l"(gptr));
}
__device__ __forceinline__ void cp_commit() { asm volatile("cp.async.commit_group;\n"); }
__device__ __forceinline__ void cp_wait0()  { asm volatile("cp.async.wait_group 0;\n"); }

__device__ __forceinline__ void ldmatrix_x4(uint32_t& r0, uint32_t& r1, uint32_t& r2, uint32_t& r3, uint32_t addr) {
    asm volatile("ldmatrix.sync.aligned.m8n8.x4.shared.b16 {%0,%1,%2,%3}, [%4];\n"
                 : "=r"(r0), "=r"(r1), "=r"(r2), "=r"(r3) : "r"(addr));
}

__device__ __forceinline__ void mma16816(float* d, const uint32_t* a, const uint32_t* b) {
    asm volatile(
        "mma.sync.aligned.m16n8k16.row.col.f32.f16.f16.f32 "
        "{%0,%1,%2,%3}, {%4,%5,%6,%7}, {%8,%9}, {%0,%1,%2,%3};\n"
        : "+f"(d[0]), "+f"(d[1]), "+f"(d[2]), "+f"(d[3])
        : "r"(a[0]), "r"(a[1]), "r"(a[2]), "r"(a[3]), "r"(b[0]), "r"(b[1]));
}

__global__ __launch_bounds__(256, 3)
void qlinear_kernel(const int*   __restrict__ packed,
                    const float* __restrict__ scales,
                    const float* __restrict__ bias,
                    float*       __restrict__ out)
{
    extern __shared__ __half smem[];
    const uint32_t smem_base = (uint32_t)__cvta_generic_to_shared(smem);

    const int tid  = threadIdx.x;
    const int lane = tid & 31;
    const int warp = tid >> 5;
    const int wm   = warp & 1;    // 2 warps along M (32 rows each)
    const int wn   = warp >> 1;   // 4 warps along N (32 cols each)

    const int bm = blockIdx.y * BM;
    const int bn = blockIdx.x * BN;

    const __half2 off1032 = __halves2half2(__ushort_as_half((unsigned short)0x6408),
                                           __ushort_as_half((unsigned short)0x6408));

    // 32x32 warp tile: mt in 0..1 (16-row), nt in 0..3 (8-col); 32 f32 acc / thread
    float acc[2][4][4];
#pragma unroll
    for (int i = 0; i < 2; i++)
#pragma unroll
        for (int j = 0; j < 4; j++)
#pragma unroll
            for (int k = 0; k < 4; k++) acc[i][j][k] = 0.f;

    // layout: A0 | A1 | B0 | B1
    // A copy: 64 rows x 8 chunks(16B) = 512 chunks / 256 thr = 2 each
    const int crow = tid >> 3;       // rows 0..31, advance 32 per i
    const int ccc  = tid & 7;
    // B dequant: thread owns n = tid&127, words kw0+2*i (i<4)
    const int b_n  = tid & 127;
    const int kw0  = tid >> 7;       // 0 or 1
    const int n_g  = bn + b_n;

    auto a_base = [&](int buf) -> uint32_t {
        return smem_base + (uint32_t)(buf * A_ELEMS * 2);
    };
    auto b_base = [&](int buf) -> uint32_t {
        return smem_base + (uint32_t)((2 * A_ELEMS + buf * B_ELEMS) * 2);
    };

    auto produce_a = [&](int buf, int kb) {
        const uint32_t ab = a_base(buf);
#pragma unroll
        for (int i = 0; i < 2; i++) {
            int row = crow + 32 * i;
            cp_async16(ab + (uint32_t)((row * STRIDE + ccc * 8) * 2),
                       g_xh + (size_t)(bm + row) * KDIM + kb + ccc * 8);
        }
        cp_commit();
    };

    uint32_t bw[4];
    auto load_b = [&](int kt) {
#pragma unroll
        for (int i = 0; i < 4; i++)
            bw[i] = (uint32_t)__ldg(packed + (size_t)(kt * 8 + kw0 + 2 * i) * NDIM + n_g);
    };
    auto dequant_b = [&](int buf, int kt) {
        float scf = __ldg(scales + (size_t)(kt >> 1) * NDIM + n_g);
        __half2 sc2 = __half2half2(__float2half_rn(scf));
        const uint32_t bb = b_base(buf) + (uint32_t)(b_n * STRIDE * 2);
#pragma unroll
        for (int i = 0; i < 4; i++) {
            uint32_t r[4];
#pragma unroll
            for (int j = 0; j < 4; j++) {
                uint32_t v = bw[i] >> (8 * j);
                uint32_t p = ((v & 0xFu) | ((v & 0xF0u) << 12)) | 0x64006400u;
                __half2 h = __hmul2(__hsub2(*(__half2*)&p, off1032), sc2);
                r[j] = *(uint32_t*)&h;
            }
            asm volatile("st.shared.v4.b32 [%0], {%1,%2,%3,%4};\n"
                         :: "r"(bb + (uint32_t)((kw0 + 2 * i) * 16)),
                            "r"(r[0]), "r"(r[1]), "r"(r[2]), "r"(r[3]));
        }
    };

    // prologue: stage 0
    produce_a(0, 0);
    load_b(0);
    dequant_b(0, 0);
    cp_wait0();
    __syncthreads();

    const int arow  = wm * 32 + (lane & 15);
    const int acolg = (lane >> 4) * 8;
    const int brow  = wn * 32 + (lane & 15);

    for (int kt = 0; kt < NUM_KT; ++kt) {
        const int buf = kt & 1;
        const bool has_next = (kt + 1) < NUM_KT;

        if (has_next) {
            produce_a(buf ^ 1, (kt + 1) * BK);   // async engine runs under compute
            load_b(kt + 1);                      // LDG latency hidden by mma below
        }

        const uint32_t ab = a_base(buf);
        const uint32_t bb = b_base(buf);
#pragma unroll
        for (int ks = 0; ks < 4; ks++) {
            uint32_t a[2][4];
#pragma unroll
            for (int mt = 0; mt < 2; mt++) {
                uint32_t addr = ab + (uint32_t)(((arow + mt * 16) * STRIDE + ks * 16 + acolg) * 2);
                ldmatrix_x4(a[mt][0], a[mt][1], a[mt][2], a[mt][3], addr);
            }
            uint32_t b[4][2];
#pragma unroll
            for (int nt2 = 0; nt2 < 2; nt2++) {
                uint32_t r0, r1, r2, r3;
                uint32_t addr = bb + (uint32_t)(((brow + nt2 * 16) * STRIDE + ks * 16 + acolg) * 2);
                ldmatrix_x4(r0, r1, r2, r3, addr);
                b[2 * nt2][0] = r0; b[2 * nt2][1] = r2;
                b[2 * nt2 + 1][0] = r1; b[2 * nt2 + 1][1] = r3;
            }
#pragma unroll
            for (int mt = 0; mt < 2; mt++)
#pragma unroll
                for (int nt = 0; nt < 4; nt++)
                    mma16816(acc[mt][nt], a[mt], b[nt]);
        }

        if (has_next) {
            dequant_b(buf ^ 1, kt + 1);   // STS into free buffer
            cp_wait0();
        }
        __syncthreads();
    }

    // ---------- epilogue: f32 out, rounded through fp16 to match reference ----------
#pragma unroll
    for (int mt = 0; mt < 2; mt++) {
#pragma unroll
        for (int nt = 0; nt < 4; nt++) {
            int row0 = bm + wm * 32 + mt * 16 + (lane >> 2);
            int col  = bn + wn * 32 + nt * 8 + (lane & 3) * 2;
            float2 bf = *(const float2*)(bias + col);
            float2 v0, v1;
            v0.x = __half2float(__float2half_rn(acc[mt][nt][0] + bf.x));
            v0.y = __half2float(__float2half_rn(acc[mt][nt][1] + bf.y));
            v1.x = __half2float(__float2half_rn(acc[mt][nt][2] + bf.x));
            v1.y = __half2float(__float2half_rn(acc[mt][nt][3] + bf.y));
            *(float2*)(out + (size_t)row0 * NDIM + col) = v0;
            *(float2*)(out + (size_t)(row0 + 8) * NDIM + col) = v1;
        }
    }
}

extern "C" void kernel_launch(void* const* d_in, const int* in_sizes, int n_in,
                              void* d_out, int out_size) {
    const float* x      = (const float*)d_in[0];
    const int*   packed = (const int*)d_in[1];
    const float* scales = (const float*)d_in[2];
    const float* bias   = (const float*)d_in[3];
    float*       out    = (float*)d_out;

    // prepass: x (f32) -> g_xh (fp16)
    const size_t n_x = (size_t)MDIM * KDIM;
    cvt_x_kernel<<<(unsigned)(n_x / 4 / 256), 256>>>(x);

    cudaFuncSetAttribute(qlinear_kernel, cudaFuncAttributeMaxDynamicSharedMemorySize, SMEM_BYTES);
    dim3 grid(NDIM / BN, MDIM / BM);
    qlinear_kernel<<<grid, 256, SMEM_BYTES>>>(packed, scales, bias, out);
}